// round 12
// baseline (speedup 1.0000x reference)
#include <cuda_runtime.h>
#include <math_constants.h>

// Outputs packed float32, reference return order:
//   [0,    N)   t_hit
//   [N,   2N)   sphere_idx (as float, -1 for miss)
//   [2N,  5N)   hit_points  (N,3)
//   [5N,  8N)   hit_normals (N,3)
//
// Two-phase: a branch-free FILTER loop computes a RELAXED discriminant
// (8 packed f32x2 ops/pair, fused/reassociated, +0.5 conservative margin)
// and shifts "possible hit" bits into per-PAIR masks. The RESOLVE pass
// scans the WARP-UNION of the masks (uniform control flow via ballot) and
// redoes the reference-exact fp32 op sequence (half-b domain; power-of-two/
// sign scalings commute exactly with rn) for those pairs. Threads without
// the flag execute the exact test too and reject naturally (q < 0), so all
// decisions are bit-identical to the reference, visited ascending j
// (first-min tie-break preserved).

#define MAX_SPH  256
#define MAX_PAIR (MAX_SPH / 2)
#define BLOCK    256

typedef unsigned long long u64;
typedef unsigned int       u32;

__device__ __forceinline__ u64 fma2(u64 a, u64 b, u64 c) {
    u64 d; asm("fma.rn.f32x2 %0, %1, %2, %3;" : "=l"(d) : "l"(a), "l"(b), "l"(c)); return d;
}
__device__ __forceinline__ u64 pkf(float lo, float hi) {
    return (u64)__float_as_uint(lo) | ((u64)__float_as_uint(hi) << 32);
}

__global__ __launch_bounds__(BLOCK, 5)
void raysphere_kernel(const float* __restrict__ ro,
                      const float* __restrict__ rd,
                      const float* __restrict__ sc,
                      const float* __restrict__ sr,
                      float* __restrict__ out,
                      int n_rays, int n_sph)
{
    // Pre-packed pair data: sXY[k] = {pack(x0,x1), pack(y0,y1)},
    //                       sZW[k] = {pack(z0,z1), pack(w0,w1)}, w = |c|^2-r^2
    __shared__ ulonglong2 sXY[MAX_PAIR];
    __shared__ ulonglong2 sZW[MAX_PAIR];
    __shared__ float4     s_ctr[MAX_SPH];

    const int tid    = threadIdx.x;
    const int n_pair = n_sph >> 1;

    for (int j = tid; j < n_sph; j += BLOCK) {
        float cx = sc[3 * j + 0];
        float cy = sc[3 * j + 1];
        float cz = sc[3 * j + 2];
        float r  = sr[j];
        float s2 = __fadd_rn(__fadd_rn(__fmul_rn(cx, cx), __fmul_rn(cy, cy)),
                             __fmul_rn(cz, cz));
        float w  = __fsub_rn(s2, __fmul_rn(r, r));
        s_ctr[j] = make_float4(cx, cy, cz, w);
    }
    __syncthreads();
    for (int k = tid; k < n_pair; k += BLOCK) {
        float4 p0 = s_ctr[2 * k], p1 = s_ctr[2 * k + 1];
        sXY[k] = make_ulonglong2(pkf(p0.x, p1.x), pkf(p0.y, p1.y));
        sZW[k] = make_ulonglong2(pkf(p0.z, p1.z), pkf(p0.w, p1.w));
    }
    __syncthreads();

    const int i = blockIdx.x * BLOCK + tid;
    if (i >= n_rays) return;

    const float ox = ro[3 * i + 0];
    const float oy = ro[3 * i + 1];
    const float oz = ro[3 * i + 2];
    const float dx = rd[3 * i + 0];
    const float dy = rd[3 * i + 1];
    const float dz = rd[3 * i + 2];

    // jnp.sum(v*v): rounded squares, left-to-right add (reference order)
    const float a   = __fadd_rn(__fadd_rn(__fmul_rn(dx, dx), __fmul_rn(dy, dy)),
                                __fmul_rn(dz, dz));
    const float ddo = __fadd_rn(__fadd_rn(__fmul_rn(dx, ox), __fmul_rn(dy, oy)),
                                __fmul_rn(dz, oz));
    const float on2 = __fadd_rn(__fadd_rn(__fmul_rn(ox, ox), __fmul_rn(oy, oy)),
                                __fmul_rn(oz, oz));
    const float n2ox = __fmul_rn(-2.0f, ox);
    const float n2oy = __fmul_rn(-2.0f, oy);
    const float n2oz = __fmul_rn(-2.0f, oz);

    // Relaxed-filter constant: -a*on2 + 0.5 margin (>> ~0.02 worst-case
    // fused-vs-exact drift for flag-relevant spheres; narrow enough to keep
    // the resolve rate near the true-hit level).
    const float kmar = __fmaf_rn(-a, on2, 0.5f);

    // Packed broadcast constants for the filter
    const u64 pndx  = pkf(-dx, -dx), pndy  = pkf(-dy, -dy), pndz  = pkf(-dz, -dz);
    const u64 pn2ox = pkf(n2ox, n2ox), pn2oy = pkf(n2oy, n2oy), pn2oz = pkf(n2oz, n2oz);
    const u64 pddo = pkf(ddo, ddo);
    const u64 pna  = pkf(-a, -a);
    const u64 pkm  = pkf(kmar, kmar);

    float best_m = CUDART_INF_F;
    float best_t = CUDART_INF_F;
    int   best_j = 0;

    // Reference-exact scalar resolve for sphere j. Safe to execute for any
    // sphere: it applies the exact reference hit conditions.
    auto resolve = [&](int j) {
        const float4 s = s_ctr[j];
        const float nddc  = __fmaf_rn(-dz, s.z,
                              __fmaf_rn(-dy, s.y, __fmul_rn(-dx, s.x)));
        const float n2odc = __fmaf_rn(n2oz, s.z,
                              __fmaf_rn(n2oy, s.y, __fmul_rn(n2ox, s.x)));
        const float x = __fadd_rn(ddo, nddc);                    // b/2
        const float c = __fadd_rn(__fadd_rn(on2, n2odc), s.w);
        const float q = __fadd_rn(__fmul_rn(x, x), __fmul_rn(-a, c)); // disc/4
        if (q >= 0.0f) {
            const float sq = __fsqrt_rn(q);                      // sqrt_disc/2
            const float m1 = __fsub_rn(-x, sq);
            const float m0 = __fadd_rn(-x, sq);
            const float m  = (m1 > 0.0f) ? m1 : m0;
            if (m > 0.0f && m < best_m) {
                best_m = m;
                const float t = __fdiv_rn(m, a);                 // == num/(2a)
                if (t < best_t) { best_t = t; best_j = j; }
            }
        }
    };

    if (n_pair == MAX_PAIR) {
        // ---- branch-free relaxed filter: 8 packed ops + 3 ALU per pair ----
        u32 msk[4];
        #pragma unroll
        for (int w = 0; w < 4; w++) {
            u32 m = 0;
            const int kb = w << 5;
            #pragma unroll 16
            for (int t = 0; t < 32; t++) {
                const ulonglong2 A = sXY[kb + t];   // {x0,x1},{y0,y1}
                const ulonglong2 B = sZW[kb + t];   // {z0,z1},{w0,w1}
                // hb ~ ddo - d.c        (3 fused ops)
                const u64 hb = fma2(pndx, A.x, fma2(pndy, A.y, fma2(pndz, B.x, pddo)));
                // cc ~ w - 2 o.c        (3 fused ops, accumulator starts at w)
                const u64 cc = fma2(pn2ox, A.x, fma2(pn2oy, A.y, fma2(pn2oz, B.x, B.y)));
                // q~ + 0.5 = hb^2 + (-a)*cc + (-a*on2 + 0.5)   (2 ops)
                const u64 qs = fma2(hb, hb, fma2(pna, cc, pkm));
                // bit = "any lane of (q~+0.5) >= 0"  (sign-bit test; -0.0f
                // cannot occur: rn cancellation yields +0)
                const u32 nb = ~((u32)qs & (u32)(qs >> 32));
                m = m * 2u + (nb >> 31);            // pair kb+t -> bit (31-t)
            }
            msk[w] = m;
        }

        // ---- resolve: WARP-UNION scan (uniform control flow) ----
        // Union mask is identical across the warp -> the while loop and clz
        // are non-divergent; resolve runs for all threads and rejects
        // non-flagged spheres via the exact q<0 test.
        #pragma unroll
        for (int w = 0; w < 4; w++) {
            u32 mu = __reduce_or_sync(0xFFFFFFFFu, msk[w]);
            while (mu) {
                const int t = __clz(mu);            // smallest pair index first
                mu &= ~(0x80000000u >> t);
                const int k = (w << 5) + t;
                resolve(2 * k);
                resolve(2 * k + 1);
            }
        }
    } else {
        // Generic fallback (any n_sph): exact scalar per sphere
        for (int j = 0; j < n_sph; j++) resolve(j);
    }

    const float t_hit = best_t;
    const bool  any   = isfinite(t_hit);

    const long long N = n_rays;
    out[i]     = t_hit;
    out[N + i] = any ? (float)best_j : -1.0f;

    // hit_points = o + t*d (mul then add — matches reference)
    const float hx = __fadd_rn(ox, __fmul_rn(t_hit, dx));
    const float hy = __fadd_rn(oy, __fmul_rn(t_hit, dy));
    const float hz = __fadd_rn(oz, __fmul_rn(t_hit, dz));
    out[2 * N + 3 * i + 0] = hx;
    out[2 * N + 3 * i + 1] = hy;
    out[2 * N + 3 * i + 2] = hz;

    const float4 cb = s_ctr[any ? best_j : 0];
    const float nx = __fsub_rn(hx, cb.x);
    const float ny = __fsub_rn(hy, cb.y);
    const float nz = __fsub_rn(hz, cb.z);
    const float nn = __fadd_rn(__fadd_rn(__fmul_rn(nx, nx), __fmul_rn(ny, ny)),
                               __fmul_rn(nz, nz));
    const float len = __fsqrt_rn(nn);
    out[5 * N + 3 * i + 0] = any ? __fdiv_rn(nx, len) : 0.0f;
    out[5 * N + 3 * i + 1] = any ? __fdiv_rn(ny, len) : 0.0f;
    out[5 * N + 3 * i + 2] = any ? __fdiv_rn(nz, len) : 0.0f;
}

extern "C" void kernel_launch(void* const* d_in, const int* in_sizes, int n_in,
                              void* d_out, int out_size)
{
    const float* ro = (const float*)d_in[0];   // (N,3)
    const float* rd = (const float*)d_in[1];   // (N,3)
    const float* sc = (const float*)d_in[2];   // (M,3)
    const float* sr = (const float*)d_in[3];   // (M,)

    const int n_rays = in_sizes[0] / 3;
    const int n_sph  = in_sizes[3];

    float* out = (float*)d_out;

    const int grid = (n_rays + BLOCK - 1) / BLOCK;
    raysphere_kernel<<<grid, BLOCK>>>(ro, rd, sc, sr, out, n_rays, n_sph);
}

// round 13
// speedup vs baseline: 1.3064x; 1.3064x over previous
#include <cuda_runtime.h>
#include <math_constants.h>

// Outputs packed float32, reference return order:
//   [0,    N)   t_hit
//   [N,   2N)   sphere_idx (as float, -1 for miss)
//   [2N,  5N)   hit_points  (N,3)
//   [5N,  8N)   hit_normals (N,3)
//
// Two-phase: a branch-free FILTER loop computes a RELAXED discriminant
// (8 packed f32x2 ops/pair, fused/reassociated, +0.5 conservative margin)
// and shifts "possible hit" bits into per-pair masks. A short RESOLVE pass
// (per-thread, divergent-rare) redoes the reference-exact fp32 op sequence
// (half-b domain; power-of-two/sign scalings commute exactly with rn) only
// for flagged pairs, ascending sphere order (reference first-min
// tie-break). Filter false positives are rejected by the exact q >= 0 test
// -> all decisions bit-identical to the reference.
// This revision: __launch_bounds__(256, 7) to raise occupancy (7 CTAs/SM).

#define MAX_SPH  256
#define MAX_PAIR (MAX_SPH / 2)
#define BLOCK    256

typedef unsigned long long u64;
typedef unsigned int       u32;

__device__ __forceinline__ u64 fma2(u64 a, u64 b, u64 c) {
    u64 d; asm("fma.rn.f32x2 %0, %1, %2, %3;" : "=l"(d) : "l"(a), "l"(b), "l"(c)); return d;
}
__device__ __forceinline__ u64 pkf(float lo, float hi) {
    return (u64)__float_as_uint(lo) | ((u64)__float_as_uint(hi) << 32);
}

__global__ __launch_bounds__(BLOCK, 7)
void raysphere_kernel(const float* __restrict__ ro,
                      const float* __restrict__ rd,
                      const float* __restrict__ sc,
                      const float* __restrict__ sr,
                      float* __restrict__ out,
                      int n_rays, int n_sph)
{
    // Pre-packed pair data: sXY[k] = {pack(x0,x1), pack(y0,y1)},
    //                       sZW[k] = {pack(z0,z1), pack(w0,w1)}, w = |c|^2-r^2
    __shared__ ulonglong2 sXY[MAX_PAIR];
    __shared__ ulonglong2 sZW[MAX_PAIR];
    __shared__ float4     s_ctr[MAX_SPH];

    const int tid    = threadIdx.x;
    const int n_pair = n_sph >> 1;

    for (int j = tid; j < n_sph; j += BLOCK) {
        float cx = sc[3 * j + 0];
        float cy = sc[3 * j + 1];
        float cz = sc[3 * j + 2];
        float r  = sr[j];
        float s2 = __fadd_rn(__fadd_rn(__fmul_rn(cx, cx), __fmul_rn(cy, cy)),
                             __fmul_rn(cz, cz));
        float w  = __fsub_rn(s2, __fmul_rn(r, r));
        s_ctr[j] = make_float4(cx, cy, cz, w);
    }
    __syncthreads();
    for (int k = tid; k < n_pair; k += BLOCK) {
        float4 p0 = s_ctr[2 * k], p1 = s_ctr[2 * k + 1];
        sXY[k] = make_ulonglong2(pkf(p0.x, p1.x), pkf(p0.y, p1.y));
        sZW[k] = make_ulonglong2(pkf(p0.z, p1.z), pkf(p0.w, p1.w));
    }
    __syncthreads();

    const int i = blockIdx.x * BLOCK + tid;
    if (i >= n_rays) return;

    const float ox = ro[3 * i + 0];
    const float oy = ro[3 * i + 1];
    const float oz = ro[3 * i + 2];
    const float dx = rd[3 * i + 0];
    const float dy = rd[3 * i + 1];
    const float dz = rd[3 * i + 2];

    // jnp.sum(v*v): rounded squares, left-to-right add (reference order)
    const float a   = __fadd_rn(__fadd_rn(__fmul_rn(dx, dx), __fmul_rn(dy, dy)),
                                __fmul_rn(dz, dz));
    const float ddo = __fadd_rn(__fadd_rn(__fmul_rn(dx, ox), __fmul_rn(dy, oy)),
                                __fmul_rn(dz, oz));
    const float on2 = __fadd_rn(__fadd_rn(__fmul_rn(ox, ox), __fmul_rn(oy, oy)),
                                __fmul_rn(oz, oz));
    const float n2ox = __fmul_rn(-2.0f, ox);
    const float n2oy = __fmul_rn(-2.0f, oy);
    const float n2oz = __fmul_rn(-2.0f, oz);

    // Relaxed-filter constant: -a*on2 + 0.5 margin (>> ~0.02 worst-case
    // fused-vs-exact drift for flag-relevant spheres; narrow enough to keep
    // the resolve rate near the true-hit level).
    const float kmar = __fmaf_rn(-a, on2, 0.5f);

    // Packed broadcast constants for the filter
    const u64 pndx  = pkf(-dx, -dx), pndy  = pkf(-dy, -dy), pndz  = pkf(-dz, -dz);
    const u64 pn2ox = pkf(n2ox, n2ox), pn2oy = pkf(n2oy, n2oy), pn2oz = pkf(n2oz, n2oz);
    const u64 pddo = pkf(ddo, ddo);
    const u64 pna  = pkf(-a, -a);
    const u64 pkm  = pkf(kmar, kmar);

    float best_m = CUDART_INF_F;
    float best_t = CUDART_INF_F;
    int   best_j = 0;

    // Reference-exact scalar resolve for sphere j.
    auto resolve = [&](int j) {
        const float4 s = s_ctr[j];
        const float nddc  = __fmaf_rn(-dz, s.z,
                              __fmaf_rn(-dy, s.y, __fmul_rn(-dx, s.x)));
        const float n2odc = __fmaf_rn(n2oz, s.z,
                              __fmaf_rn(n2oy, s.y, __fmul_rn(n2ox, s.x)));
        const float x = __fadd_rn(ddo, nddc);                    // b/2
        const float c = __fadd_rn(__fadd_rn(on2, n2odc), s.w);
        const float q = __fadd_rn(__fmul_rn(x, x), __fmul_rn(-a, c)); // disc/4
        if (q >= 0.0f) {
            const float sq = __fsqrt_rn(q);                      // sqrt_disc/2
            const float m1 = __fsub_rn(-x, sq);
            const float m0 = __fadd_rn(-x, sq);
            const float m  = (m1 > 0.0f) ? m1 : m0;
            if (m > 0.0f && m < best_m) {
                best_m = m;
                const float t = __fdiv_rn(m, a);                 // == num/(2a)
                if (t < best_t) { best_t = t; best_j = j; }
            }
        }
    };

    if (n_pair == MAX_PAIR) {
        // ---- branch-free relaxed filter: 8 packed ops + 3 ALU per pair ----
        u32 msk[4];
        #pragma unroll
        for (int w = 0; w < 4; w++) {
            u32 m = 0;
            const int kb = w << 5;
            #pragma unroll 8
            for (int t = 0; t < 32; t++) {
                const ulonglong2 A = sXY[kb + t];   // {x0,x1},{y0,y1}
                const ulonglong2 B = sZW[kb + t];   // {z0,z1},{w0,w1}
                // hb ~ ddo - d.c        (3 fused ops)
                const u64 hb = fma2(pndx, A.x, fma2(pndy, A.y, fma2(pndz, B.x, pddo)));
                // cc ~ w - 2 o.c        (3 fused ops, accumulator starts at w)
                const u64 cc = fma2(pn2ox, A.x, fma2(pn2oy, A.y, fma2(pn2oz, B.x, B.y)));
                // q~ + 0.5 = hb^2 + (-a)*cc + (-a*on2 + 0.5)   (2 ops)
                const u64 qs = fma2(hb, hb, fma2(pna, cc, pkm));
                // bit = "any lane of (q~+0.5) >= 0"  (sign-bit test; -0.0f
                // cannot occur: rn cancellation yields +0)
                const u32 nb = ~((u32)qs & (u32)(qs >> 32));
                m = m * 2u + (nb >> 31);            // pair kb+t -> bit (31-t)
            }
            msk[w] = m;
        }

        // ---- resolve flagged pairs, ascending k (MSB-first scan) ----
        #pragma unroll
        for (int w = 0; w < 4; w++) {
            u32 m = msk[w];
            while (m) {
                const int t = __clz(m);             // smallest pair index first
                m &= ~(0x80000000u >> t);
                const int k = (w << 5) + t;
                resolve(2 * k);
                resolve(2 * k + 1);
            }
        }
    } else {
        // Generic fallback (any n_sph): exact scalar per sphere
        for (int j = 0; j < n_sph; j++) resolve(j);
    }

    const float t_hit = best_t;
    const bool  any   = isfinite(t_hit);

    const long long N = n_rays;
    out[i]     = t_hit;
    out[N + i] = any ? (float)best_j : -1.0f;

    // hit_points = o + t*d (mul then add — matches reference)
    const float hx = __fadd_rn(ox, __fmul_rn(t_hit, dx));
    const float hy = __fadd_rn(oy, __fmul_rn(t_hit, dy));
    const float hz = __fadd_rn(oz, __fmul_rn(t_hit, dz));
    out[2 * N + 3 * i + 0] = hx;
    out[2 * N + 3 * i + 1] = hy;
    out[2 * N + 3 * i + 2] = hz;

    const float4 cb = s_ctr[any ? best_j : 0];
    const float nx = __fsub_rn(hx, cb.x);
    const float ny = __fsub_rn(hy, cb.y);
    const float nz = __fsub_rn(hz, cb.z);
    const float nn = __fadd_rn(__fadd_rn(__fmul_rn(nx, nx), __fmul_rn(ny, ny)),
                               __fmul_rn(nz, nz));
    const float len = __fsqrt_rn(nn);
    out[5 * N + 3 * i + 0] = any ? __fdiv_rn(nx, len) : 0.0f;
    out[5 * N + 3 * i + 1] = any ? __fdiv_rn(ny, len) : 0.0f;
    out[5 * N + 3 * i + 2] = any ? __fdiv_rn(nz, len) : 0.0f;
}

extern "C" void kernel_launch(void* const* d_in, const int* in_sizes, int n_in,
                              void* d_out, int out_size)
{
    const float* ro = (const float*)d_in[0];   // (N,3)
    const float* rd = (const float*)d_in[1];   // (N,3)
    const float* sc = (const float*)d_in[2];   // (M,3)
    const float* sr = (const float*)d_in[3];   // (M,)

    const int n_rays = in_sizes[0] / 3;
    const int n_sph  = in_sizes[3];

    float* out = (float*)d_out;

    const int grid = (n_rays + BLOCK - 1) / BLOCK;
    raysphere_kernel<<<grid, BLOCK>>>(ro, rd, sc, sr, out, n_rays, n_sph);
}